// round 3
// baseline (speedup 1.0000x reference)
#include <cuda_runtime.h>
#include <math.h>

#define NH   16
#define HD   64
#define KW   13
#define CDIM 1024
#define BB   4
#define LL   4096
#define QK_SCALE 0.125f   // 64^-0.5
#define RPB_W (2*KW-1)    // 25

// ---------------- scratch (device globals; no allocation allowed) ------------
__device__ float g_q[(size_t)BB*NH*LL*HD];
__device__ float g_k[(size_t)BB*NH*LL*HD];
__device__ float g_v[(size_t)BB*NH*LL*HD];
__device__ float g_attn[(size_t)BB*LL*CDIM];

// ---------------- SGEMM 128x128x8, 256 thr, 8x8 microtile, double-buffered --
// C[M,N] = A[M,K] * B[K,N]; M,N multiples of 128, K multiple of 8.
// MODE 0: A = x (arg), QKV epilogue (scatter into g_q/g_k/g_v, scale q, +bias)
// MODE 1: A = g_attn (device global), plain epilogue into C with bias

template<int MODE>
__global__ __launch_bounds__(256, 2)
void sgemm_kernel(const float* __restrict__ Aarg, const float* __restrict__ Bm,
                  const float* __restrict__ bias, float* __restrict__ C,
                  int M, int N, int K)
{
    __shared__ float As[2][8][128];   // transposed A tiles
    __shared__ float Bs[2][8][128];

    const float* __restrict__ A = (MODE == 1) ? (const float*)g_attn : Aarg;

    const int tid = threadIdx.x;
    const int tx  = tid & 15;       // 0..15 (col group)
    const int ty  = tid >> 4;       // 0..15 (row group)
    const int m0  = blockIdx.y * 128;
    const int n0  = blockIdx.x * 128;

    // A-tile load: thread -> (row=tid/2, 4 floats at col (tid&1)*4)
    const int a_row = tid >> 1;
    const int a_col = (tid & 1) * 4;
    // B-tile load: thread -> (row=tid/32, 4 floats at col (tid&31)*4)
    const int b_row = tid >> 5;
    const int b_col = (tid & 31) * 4;

    float acc[8][8];
    #pragma unroll
    for (int i = 0; i < 8; i++)
        #pragma unroll
        for (int j = 0; j < 8; j++) acc[i][j] = 0.f;

    const float* Aptr = A + (size_t)(m0 + a_row) * K + a_col;
    const float* Bptr = Bm + (size_t)b_row * N + n0 + b_col;

    const int steps = K >> 3;

    // preload slab 0
    {
        float4 av = *(const float4*)(Aptr);
        float4 bv = *(const float4*)(Bptr);
        As[0][a_col + 0][a_row] = av.x;
        As[0][a_col + 1][a_row] = av.y;
        As[0][a_col + 2][a_row] = av.z;
        As[0][a_col + 3][a_row] = av.w;
        *(float4*)&Bs[0][b_row][b_col] = bv;
    }
    __syncthreads();

    for (int s = 0; s < steps; s++) {
        const int buf = s & 1;
        float4 an, bn;
        const bool has_next = (s + 1 < steps);
        if (has_next) {
            an = *(const float4*)(Aptr + (s + 1) * 8);
            bn = *(const float4*)(Bptr + (size_t)(s + 1) * 8 * N);
        }

        #pragma unroll
        for (int kk = 0; kk < 8; kk++) {
            float a[8], b[8];
            float4 t0 = *(const float4*)&As[buf][kk][ty * 8];
            float4 t1 = *(const float4*)&As[buf][kk][ty * 8 + 4];
            a[0]=t0.x; a[1]=t0.y; a[2]=t0.z; a[3]=t0.w;
            a[4]=t1.x; a[5]=t1.y; a[6]=t1.z; a[7]=t1.w;
            float4 u0 = *(const float4*)&Bs[buf][kk][tx * 8];
            float4 u1 = *(const float4*)&Bs[buf][kk][tx * 8 + 4];
            b[0]=u0.x; b[1]=u0.y; b[2]=u0.z; b[3]=u0.w;
            b[4]=u1.x; b[5]=u1.y; b[6]=u1.z; b[7]=u1.w;
            #pragma unroll
            for (int i = 0; i < 8; i++)
                #pragma unroll
                for (int j = 0; j < 8; j++)
                    acc[i][j] = fmaf(a[i], b[j], acc[i][j]);
        }

        if (has_next) {
            const int nxt = buf ^ 1;
            As[nxt][a_col + 0][a_row] = an.x;
            As[nxt][a_col + 1][a_row] = an.y;
            As[nxt][a_col + 2][a_row] = an.z;
            As[nxt][a_col + 3][a_row] = an.w;
            *(float4*)&Bs[nxt][b_row][b_col] = bn;
            __syncthreads();
        }
    }

    // epilogue
    #pragma unroll
    for (int i = 0; i < 8; i++) {
        const int m = m0 + ty * 8 + i;
        #pragma unroll
        for (int j = 0; j < 8; j++) {
            const int n = n0 + tx * 8 + j;
            float val = acc[i][j] + bias[n];
            if (MODE == 0) {
                const int b_  = m >> 12;        // m / L (L=4096)
                const int l   = m & (LL - 1);
                const int wch = n >> 10;        // 0=q 1=k 2=v
                const int rem = n & 1023;
                const int h   = rem >> 6;
                const int d   = rem & 63;
                const size_t idx = (((size_t)(b_ * NH + h)) * LL + l) * HD + d;
                if (wch == 0)      g_q[idx] = val * QK_SCALE;
                else if (wch == 1) g_k[idx] = val;
                else               g_v[idx] = val;
            } else {
                C[(size_t)m * N + n] = val;
            }
        }
    }
}

// ---------------- NA1D attention ------------------------------------------
// block = 128 queries of one (b,h). Two-phase: K tile -> logits, then the SAME
// smem buffer is reloaded with the V tile (halves smem; fits static 48KB).
#define TROWS 140
#define ROWP  65   // padded row stride to kill bank conflicts

__global__ __launch_bounds__(128, 1)
void na1d_kernel(const float* __restrict__ rpb)
{
    __shared__ float tile[TROWS * ROWP];   // K tile, then V tile
    __shared__ float rsh[RPB_W];

    const int tid = threadIdx.x;
    const int l0  = blockIdx.x * 128;
    const int h   = blockIdx.y;
    const int b   = blockIdx.z;

    const size_t head_base = ((size_t)(b * NH + h)) * LL * HD;
    const int kbase = min(max(l0 - (KW / 2), 0), LL - KW);
    const int krows = min(TROWS, LL - kbase);

    // ---- phase 1: load K tile ----
    const float* kp = g_k + head_base + (size_t)kbase * HD;
    for (int idx = tid; idx < krows * 16; idx += 128) {
        const int r  = idx >> 4;
        const int c4 = (idx & 15) * 4;
        float4 kv = *(const float4*)(kp + (size_t)r * HD + c4);
        float* kd = &tile[r * ROWP + c4];
        kd[0]=kv.x; kd[1]=kv.y; kd[2]=kv.z; kd[3]=kv.w;
    }
    if (tid < RPB_W) rsh[tid] = rpb[h * RPB_W + tid];
    __syncthreads();

    const int l = l0 + tid;
    float qreg[HD];
    const float* qp = g_q + head_base + (size_t)l * HD;
    #pragma unroll
    for (int c4 = 0; c4 < 16; c4++) {
        float4 qv = *(const float4*)(qp + c4 * 4);
        qreg[c4*4+0]=qv.x; qreg[c4*4+1]=qv.y; qreg[c4*4+2]=qv.z; qreg[c4*4+3]=qv.w;
    }

    const int ni = min(max(l - (KW / 2), 0), LL - KW);
    const int r0 = ni - kbase;
    const int bias0 = ni - l + (KW - 1);

    float logits[KW];
    #pragma unroll
    for (int kk = 0; kk < KW; kk++) {
        const float* kr = &tile[(r0 + kk) * ROWP];
        float s = 0.f;
        #pragma unroll
        for (int d = 0; d < HD; d++) s = fmaf(qreg[d], kr[d], s);
        logits[kk] = s + rsh[bias0 + kk];
    }

    float mx = logits[0];
    #pragma unroll
    for (int kk = 1; kk < KW; kk++) mx = fmaxf(mx, logits[kk]);
    float ssum = 0.f;
    #pragma unroll
    for (int kk = 0; kk < KW; kk++) { logits[kk] = expf(logits[kk] - mx); ssum += logits[kk]; }
    const float inv = 1.f / ssum;

    // ---- phase 2: reload the same smem with V tile ----
    __syncthreads();
    const float* vp = g_v + head_base + (size_t)kbase * HD;
    for (int idx = tid; idx < krows * 16; idx += 128) {
        const int r  = idx >> 4;
        const int c4 = (idx & 15) * 4;
        float4 vv = *(const float4*)(vp + (size_t)r * HD + c4);
        float* vd = &tile[r * ROWP + c4];
        vd[0]=vv.x; vd[1]=vv.y; vd[2]=vv.z; vd[3]=vv.w;
    }
    __syncthreads();

    float accv[HD];
    #pragma unroll
    for (int d = 0; d < HD; d++) accv[d] = 0.f;
    #pragma unroll
    for (int kk = 0; kk < KW; kk++) {
        const float w = logits[kk] * inv;
        const float* vr = &tile[(r0 + kk) * ROWP];
        #pragma unroll
        for (int d = 0; d < HD; d++) accv[d] = fmaf(w, vr[d], accv[d]);
    }

    float* op = g_attn + ((size_t)b * LL + l) * CDIM + h * HD;
    #pragma unroll
    for (int c4 = 0; c4 < 16; c4++) {
        float4 ov;
        ov.x = accv[c4*4+0]; ov.y = accv[c4*4+1];
        ov.z = accv[c4*4+2]; ov.w = accv[c4*4+3];
        *(float4*)(op + c4 * 4) = ov;
    }
}

// ---------------- launch ----------------------------------------------------
extern "C" void kernel_launch(void* const* d_in, const int* in_sizes, int n_in,
                              void* d_out, int out_size)
{
    const float* x      = (const float*)d_in[0];
    const float* w_qkv  = (const float*)d_in[1];
    const float* b_qkv  = (const float*)d_in[2];
    const float* rpb    = (const float*)d_in[3];
    const float* w_proj = (const float*)d_in[4];
    const float* b_proj = (const float*)d_in[5];
    float* out = (float*)d_out;

    const int M = BB * LL;          // 16384

    // 1) QKV GEMM: [M,1024] x [1024,3072] -> scatter to g_q/g_k/g_v
    {
        dim3 grid(3 * CDIM / 128, M / 128);
        sgemm_kernel<0><<<grid, 256>>>(x, w_qkv, b_qkv, nullptr, M, 3 * CDIM, CDIM);
    }

    // 2) NA1D attention -> g_attn
    {
        dim3 grid(LL / 128, NH, BB);
        na1d_kernel<<<grid, 128>>>(rpb);
    }

    // 3) proj GEMM: g_attn [M,1024] x [1024,1024] -> d_out
    {
        dim3 grid(CDIM / 128, M / 128);
        sgemm_kernel<1><<<grid, 256>>>(nullptr, w_proj, b_proj, out, M, CDIM, CDIM);
    }
}

// round 5
// speedup vs baseline: 1.9385x; 1.9385x over previous
#include <cuda_runtime.h>
#include <cuda_bf16.h>
#include <math.h>
#include <stdint.h>

#define NH   16
#define HD   64
#define KW   13
#define CDIM 1024
#define BB   4
#define LL   4096
#define MM   (BB*LL)        // 16384
#define NQKV (3*CDIM)       // 3072
#define QK_SCALE 0.125f
#define RPB_W (2*KW-1)      // 25

// ---------------- device-global scratch (no allocation allowed) --------------
__device__ float g_q[(size_t)BB*NH*LL*HD];
__device__ float g_k[(size_t)BB*NH*LL*HD];
__device__ float g_v[(size_t)BB*NH*LL*HD];

__device__ __nv_bfloat16 g_xhi[(size_t)MM*CDIM];
__device__ __nv_bfloat16 g_xlo[(size_t)MM*CDIM];
__device__ __nv_bfloat16 g_ahi[(size_t)MM*CDIM];
__device__ __nv_bfloat16 g_alo[(size_t)MM*CDIM];

__device__ __nv_bfloat16 g_wqkvT_hi[(size_t)NQKV*CDIM];
__device__ __nv_bfloat16 g_wqkvT_lo[(size_t)NQKV*CDIM];
__device__ __nv_bfloat16 g_wprojT_hi[(size_t)CDIM*CDIM];
__device__ __nv_bfloat16 g_wprojT_lo[(size_t)CDIM*CDIM];

// ---------------- warp-MMA helpers (sm_80+ ISA, valid on sm_103 target) ------
__device__ __forceinline__ uint32_t smem_u32(const void* p) {
    uint32_t a;
    asm("{ .reg .u64 t; cvta.to.shared.u64 t, %1; cvt.u32.u64 %0, t; }"
        : "=r"(a) : "l"(p));
    return a;
}
__device__ __forceinline__ void ldsm4(uint32_t* r, uint32_t addr) {
    asm volatile("ldmatrix.sync.aligned.m8n8.x4.shared.b16 {%0,%1,%2,%3}, [%4];"
        : "=r"(r[0]), "=r"(r[1]), "=r"(r[2]), "=r"(r[3]) : "r"(addr));
}
__device__ __forceinline__ void ldsm2(uint32_t* r, uint32_t addr) {
    asm volatile("ldmatrix.sync.aligned.m8n8.x2.shared.b16 {%0,%1}, [%2];"
        : "=r"(r[0]), "=r"(r[1]) : "r"(addr));
}
__device__ __forceinline__ void mma16816(float* c, const uint32_t* a, const uint32_t* b) {
    asm volatile("mma.sync.aligned.m16n8k16.row.col.f32.bf16.bf16.f32 "
        "{%0,%1,%2,%3}, {%4,%5,%6,%7}, {%8,%9}, {%0,%1,%2,%3};"
        : "+f"(c[0]), "+f"(c[1]), "+f"(c[2]), "+f"(c[3])
        : "r"(a[0]), "r"(a[1]), "r"(a[2]), "r"(a[3]), "r"(b[0]), "r"(b[1]));
}

// ---------------- pre-pass: split fp32 -> bf16 hi/lo ------------------------
// DST 0: x -> g_xhi/g_xlo
template<int DST>
__global__ __launch_bounds__(256, 4)
void split_kernel(const float* __restrict__ src, int n4)
{
    __nv_bfloat16* hi = g_xhi;
    __nv_bfloat16* lo = g_xlo;
    const int i = blockIdx.x * 256 + threadIdx.x;
    if (i >= n4) return;
    float4 v = ((const float4*)src)[i];
    __nv_bfloat16 h0 = __float2bfloat16(v.x);
    __nv_bfloat16 h1 = __float2bfloat16(v.y);
    __nv_bfloat16 h2 = __float2bfloat16(v.z);
    __nv_bfloat16 h3 = __float2bfloat16(v.w);
    hi[i*4+0] = h0; hi[i*4+1] = h1; hi[i*4+2] = h2; hi[i*4+3] = h3;
    lo[i*4+0] = __float2bfloat16(v.x - __bfloat162float(h0));
    lo[i*4+1] = __float2bfloat16(v.y - __bfloat162float(h1));
    lo[i*4+2] = __float2bfloat16(v.z - __bfloat162float(h2));
    lo[i*4+3] = __float2bfloat16(v.w - __bfloat162float(h3));
}

// ---------------- pre-pass: transpose-split weights [K,N] -> [N,K] ----------
// DST 0: w_qkv -> g_wqkvT_*, DST 1: w_proj -> g_wprojT_*
template<int DST>
__global__ __launch_bounds__(256, 4)
void transpose_split_kernel(const float* __restrict__ w, int K, int N)
{
    __nv_bfloat16* hiT = DST ? g_wprojT_hi : g_wqkvT_hi;
    __nv_bfloat16* loT = DST ? g_wprojT_lo : g_wqkvT_lo;
    __shared__ float t[32][33];
    const int n0 = blockIdx.x * 32;
    const int k0 = blockIdx.y * 32;
    const int tx = threadIdx.x;           // 0..31
    const int ty = threadIdx.y;           // 0..7
    #pragma unroll
    for (int i = 0; i < 4; i++) {
        const int k = k0 + ty + i * 8;
        t[ty + i*8][tx] = w[(size_t)k * N + n0 + tx];
    }
    __syncthreads();
    #pragma unroll
    for (int i = 0; i < 4; i++) {
        const int n = n0 + ty + i * 8;
        const float v = t[tx][ty + i*8];
        __nv_bfloat16 h = __float2bfloat16(v);
        hiT[(size_t)n * K + k0 + tx] = h;
        loT[(size_t)n * K + k0 + tx] = __float2bfloat16(v - __bfloat162float(h));
    }
}

// ---------------- bf16 3-split tensor-core GEMM ------------------------------
// C[M,N] = A[M,K] * B[N,K]^T, 128x128x32 CTA tile, 8 warps (2x4), 64x32/warp.
// 3 terms: Ahi*Bhi + Alo*Bhi + Ahi*Blo, fp32 accumulate.
// MODE 0: A = x(hi/lo), B = w_qkvT; epilogue scatters q/k/v (+bias, q scale)
// MODE 1: A = attn(hi/lo), B = w_projT; epilogue +bias into C

#define BK  32
#define LDA 40    // padded smem stride (bf16 elems)

template<int MODE>
__global__ __launch_bounds__(256, 2)
void gemm_mma_kernel(const float* __restrict__ bias, float* __restrict__ C)
{
    __shared__ __nv_bfloat16 sAhi[128*LDA];
    __shared__ __nv_bfloat16 sAlo[128*LDA];
    __shared__ __nv_bfloat16 sBhi[128*LDA];
    __shared__ __nv_bfloat16 sBlo[128*LDA];

    const __nv_bfloat16* __restrict__ Ahi = MODE ? g_ahi : g_xhi;
    const __nv_bfloat16* __restrict__ Alo = MODE ? g_alo : g_xlo;
    const __nv_bfloat16* __restrict__ Bhi = MODE ? g_wprojT_hi : g_wqkvT_hi;
    const __nv_bfloat16* __restrict__ Blo = MODE ? g_wprojT_lo : g_wqkvT_lo;

    const int tid = threadIdx.x;
    const int wid = tid >> 5;
    const int lid = tid & 31;
    const int wm  = wid & 1;         // 0..1  (M)
    const int wn  = wid >> 1;        // 0..3  (N)
    const int m0  = blockIdx.y * 128;
    const int n0  = blockIdx.x * 128;

    // gmem load mapping: 64 rows/pass, 8 bf16 (16B) per thread
    const int lrow = tid >> 2;            // 0..63
    const int lcol = (tid & 3) * 8;       // 0,8,16,24

    const uint32_t uAhi = smem_u32(sAhi);
    const uint32_t uAlo = smem_u32(sAlo);
    const uint32_t uBhi = smem_u32(sBhi);
    const uint32_t uBlo = smem_u32(sBlo);

    // ldmatrix lane addressing
    const int aRow  = wm * 64 + (lid & 15);
    const int aKoff = (lid >> 4) * 8;
    const int bRow  = wn * 32 + (lid & 7);
    const int bKoff = ((lid >> 3) & 1) * 8;

    float acc[4][4][4];
    #pragma unroll
    for (int t = 0; t < 4; t++)
        #pragma unroll
        for (int u = 0; u < 4; u++)
            #pragma unroll
            for (int e = 0; e < 4; e++) acc[t][u][e] = 0.f;

    for (int k0 = 0; k0 < CDIM; k0 += BK) {
        // ---- load chunk into smem ----
        #pragma unroll
        for (int p = 0; p < 2; p++) {
            const int row = lrow + p * 64;
            const size_t ga = (size_t)(m0 + row) * CDIM + k0 + lcol;
            const size_t gb = (size_t)(n0 + row) * CDIM + k0 + lcol;
            const int so = row * LDA + lcol;
            *(uint4*)&sAhi[so] = *(const uint4*)&Ahi[ga];
            *(uint4*)&sAlo[so] = *(const uint4*)&Alo[ga];
            *(uint4*)&sBhi[so] = *(const uint4*)&Bhi[gb];
            *(uint4*)&sBlo[so] = *(const uint4*)&Blo[gb];
        }
        __syncthreads();

        #pragma unroll
        for (int s = 0; s < 2; s++) {
            const int ak = aKoff + s * 16;
            const int bk = bKoff + s * 16;
            uint32_t ah[4][4], al[4][4], bh[4][2], bl[4][2];

            #pragma unroll
            for (int t = 0; t < 4; t++)
                ldsm4(ah[t], uAhi + (uint32_t)(((aRow + t*16) * LDA + ak) * 2));
            #pragma unroll
            for (int u = 0; u < 4; u++)
                ldsm2(bh[u], uBhi + (uint32_t)(((bRow + u*8) * LDA + bk) * 2));
            #pragma unroll
            for (int t = 0; t < 4; t++)
                #pragma unroll
                for (int u = 0; u < 4; u++)
                    mma16816(acc[t][u], ah[t], bh[u]);          // hi*hi

            #pragma unroll
            for (int t = 0; t < 4; t++)
                ldsm4(al[t], uAlo + (uint32_t)(((aRow + t*16) * LDA + ak) * 2));
            #pragma unroll
            for (int t = 0; t < 4; t++)
                #pragma unroll
                for (int u = 0; u < 4; u++)
                    mma16816(acc[t][u], al[t], bh[u]);          // lo*hi

            #pragma unroll
            for (int u = 0; u < 4; u++)
                ldsm2(bl[u], uBlo + (uint32_t)(((bRow + u*8) * LDA + bk) * 2));
            #pragma unroll
            for (int t = 0; t < 4; t++)
                #pragma unroll
                for (int u = 0; u < 4; u++)
                    mma16816(acc[t][u], ah[t], bl[u]);          // hi*lo
        }
        __syncthreads();
    }

    // ---- epilogue ----
    const int g   = lid >> 2;      // 0..7
    const int tig = lid & 3;       // 0..3
    #pragma unroll
    for (int t = 0; t < 4; t++) {
        #pragma unroll
        for (int u = 0; u < 4; u++) {
            #pragma unroll
            for (int e = 0; e < 4; e++) {
                const int m = m0 + wm*64 + t*16 + g + ((e >> 1) ? 8 : 0);
                const int n = n0 + wn*32 + u*8 + tig*2 + (e & 1);
                const float val = acc[t][u][e] + bias[n];
                if (MODE == 0) {
                    const int b_  = m >> 12;
                    const int l   = m & (LL - 1);
                    const int wch = n >> 10;
                    const int rem = n & 1023;
                    const int h   = rem >> 6;
                    const int dd  = rem & 63;
                    const size_t idx = (((size_t)(b_ * NH + h)) * LL + l) * HD + dd;
                    if (wch == 0)      g_q[idx] = val * QK_SCALE;
                    else if (wch == 1) g_k[idx] = val;
                    else               g_v[idx] = val;
                } else {
                    C[(size_t)m * CDIM + n] = val;
                }
            }
        }
    }
}

// ---------------- NA1D attention ---------------------------------------------
#define TROWS 140
#define ROWP  65

__global__ __launch_bounds__(128, 1)
void na1d_kernel(const float* __restrict__ rpb)
{
    __shared__ float tile[TROWS * ROWP];
    __shared__ float rsh[RPB_W];

    const int tid = threadIdx.x;
    const int l0  = blockIdx.x * 128;
    const int h   = blockIdx.y;
    const int b   = blockIdx.z;

    const size_t head_base = ((size_t)(b * NH + h)) * LL * HD;
    const int kbase = min(max(l0 - (KW / 2), 0), LL - KW);
    const int krows = min(TROWS, LL - kbase);

    const float* kp = g_k + head_base + (size_t)kbase * HD;
    for (int idx = tid; idx < krows * 16; idx += 128) {
        const int rr = idx >> 4;
        const int c4 = (idx & 15) * 4;
        float4 kv = *(const float4*)(kp + (size_t)rr * HD + c4);
        float* kd = &tile[rr * ROWP + c4];
        kd[0]=kv.x; kd[1]=kv.y; kd[2]=kv.z; kd[3]=kv.w;
    }
    if (tid < RPB_W) rsh[tid] = rpb[h * RPB_W + tid];
    __syncthreads();

    const int l = l0 + tid;
    float qreg[HD];
    const float* qp = g_q + head_base + (size_t)l * HD;
    #pragma unroll
    for (int c4 = 0; c4 < 16; c4++) {
        float4 qv = *(const float4*)(qp + c4 * 4);
        qreg[c4*4+0]=qv.x; qreg[c4*4+1]=qv.y; qreg[c4*4+2]=qv.z; qreg[c4*4+3]=qv.w;
    }

    const int ni = min(max(l - (KW / 2), 0), LL - KW);
    const int r0 = ni - kbase;
    const int bias0 = ni - l + (KW - 1);

    float logits[KW];
    #pragma unroll
    for (int kk = 0; kk < KW; kk++) {
        const float* kr = &tile[(r0 + kk) * ROWP];
        float s = 0.f;
        #pragma unroll
        for (int d = 0; d < HD; d++) s = fmaf(qreg[d], kr[d], s);
        logits[kk] = s + rsh[bias0 + kk];
    }

    float mx = logits[0];
    #pragma unroll
    for (int kk = 1; kk < KW; kk++) mx = fmaxf(mx, logits[kk]);
    float ssum = 0.f;
    #pragma unroll
    for (int kk = 0; kk < KW; kk++) { logits[kk] = expf(logits[kk] - mx); ssum += logits[kk]; }
    const float inv = 1.f / ssum;

    __syncthreads();
    const float* vp = g_v + head_base + (size_t)kbase * HD;
    for (int idx = tid; idx < krows * 16; idx += 128) {
        const int rr = idx >> 4;
        const int c4 = (idx & 15) * 4;
        float4 vv = *(const float4*)(vp + (size_t)rr * HD + c4);
        float* vd = &tile[rr * ROWP + c4];
        vd[0]=vv.x; vd[1]=vv.y; vd[2]=vv.z; vd[3]=vv.w;
    }
    __syncthreads();

    float accv[HD];
    #pragma unroll
    for (int d = 0; d < HD; d++) accv[d] = 0.f;
    #pragma unroll
    for (int kk = 0; kk < KW; kk++) {
        const float w = logits[kk] * inv;
        const float* vr = &tile[(r0 + kk) * ROWP];
        #pragma unroll
        for (int d = 0; d < HD; d++) accv[d] = fmaf(w, vr[d], accv[d]);
    }

    // write bf16 hi/lo into [B, L, H*D] for the proj GEMM
    const size_t obase = ((size_t)b * LL + l) * CDIM + h * HD;
    __nv_bfloat16* oh = g_ahi + obase;
    __nv_bfloat16* ol = g_alo + obase;
    #pragma unroll
    for (int d = 0; d < HD; d++) {
        const float v = accv[d];
        __nv_bfloat16 hh = __float2bfloat16(v);
        oh[d] = hh;
        ol[d] = __float2bfloat16(v - __bfloat162float(hh));
    }
}

// ---------------- launch ------------------------------------------------------
extern "C" void kernel_launch(void* const* d_in, const int* in_sizes, int n_in,
                              void* d_out, int out_size)
{
    const float* x      = (const float*)d_in[0];
    const float* w_qkv  = (const float*)d_in[1];
    const float* b_qkv  = (const float*)d_in[2];
    const float* rpb    = (const float*)d_in[3];
    const float* w_proj = (const float*)d_in[4];
    const float* b_proj = (const float*)d_in[5];
    float* out = (float*)d_out;

    // 0) split x into bf16 hi/lo
    {
        const int n4 = MM * CDIM / 4;
        split_kernel<0><<<(n4 + 255) / 256, 256>>>(x, n4);
    }
    // 0b) transpose+split weights
    {
        dim3 grid(NQKV / 32, CDIM / 32);
        transpose_split_kernel<0><<<grid, dim3(32, 8)>>>(w_qkv, CDIM, NQKV);
        dim3 grid2(CDIM / 32, CDIM / 32);
        transpose_split_kernel<1><<<grid2, dim3(32, 8)>>>(w_proj, CDIM, CDIM);
    }

    // 1) QKV GEMM (tensor cores) -> scatter q/k/v
    {
        dim3 grid(NQKV / 128, MM / 128);
        gemm_mma_kernel<0><<<grid, 256>>>(b_qkv, nullptr);
    }

    // 2) NA1D attention -> bf16 hi/lo attn output
    {
        dim3 grid(LL / 128, NH, BB);
        na1d_kernel<<<grid, 128>>>(rpb);
    }

    // 3) proj GEMM (tensor cores) -> d_out
    {
        dim3 grid(CDIM / 128, MM / 128);
        gemm_mma_kernel<1><<<grid, 256>>>(b_proj, out);
    }
}

// round 6
// speedup vs baseline: 2.1814x; 1.1253x over previous
#include <cuda_runtime.h>
#include <cuda_bf16.h>
#include <math.h>
#include <stdint.h>

#define NH   16
#define HD   64
#define KW   13
#define CDIM 1024
#define BB   4
#define LL   4096
#define MM   (BB*LL)        // 16384
#define NQKV (3*CDIM)       // 3072
#define QK_SCALE 0.125f
#define RPB_W (2*KW-1)      // 25

// ---------------- device-global scratch (no allocation allowed) --------------
__device__ float g_q[(size_t)BB*NH*LL*HD];
__device__ float g_k[(size_t)BB*NH*LL*HD];
__device__ float g_v[(size_t)BB*NH*LL*HD];

__device__ __nv_bfloat16 g_xhi[(size_t)MM*CDIM];
__device__ __nv_bfloat16 g_xlo[(size_t)MM*CDIM];
__device__ __nv_bfloat16 g_ahi[(size_t)MM*CDIM];
__device__ __nv_bfloat16 g_alo[(size_t)MM*CDIM];

__device__ __nv_bfloat16 g_wqkvT_hi[(size_t)NQKV*CDIM];
__device__ __nv_bfloat16 g_wqkvT_lo[(size_t)NQKV*CDIM];
__device__ __nv_bfloat16 g_wprojT_hi[(size_t)CDIM*CDIM];
__device__ __nv_bfloat16 g_wprojT_lo[(size_t)CDIM*CDIM];

// ---------------- helpers (sm_80+ ISA, valid on sm_103 target) ---------------
__device__ __forceinline__ uint32_t smem_u32(const void* p) {
    uint32_t a;
    asm("{ .reg .u64 t; cvta.to.shared.u64 t, %1; cvt.u32.u64 %0, t; }"
        : "=r"(a) : "l"(p));
    return a;
}
__device__ __forceinline__ void ldsm4(uint32_t* r, uint32_t addr) {
    asm volatile("ldmatrix.sync.aligned.m8n8.x4.shared.b16 {%0,%1,%2,%3}, [%4];"
        : "=r"(r[0]), "=r"(r[1]), "=r"(r[2]), "=r"(r[3]) : "r"(addr));
}
__device__ __forceinline__ void ldsm2(uint32_t* r, uint32_t addr) {
    asm volatile("ldmatrix.sync.aligned.m8n8.x2.shared.b16 {%0,%1}, [%2];"
        : "=r"(r[0]), "=r"(r[1]) : "r"(addr));
}
__device__ __forceinline__ void mma16816(float* c, const uint32_t* a, const uint32_t* b) {
    asm volatile("mma.sync.aligned.m16n8k16.row.col.f32.bf16.bf16.f32 "
        "{%0,%1,%2,%3}, {%4,%5,%6,%7}, {%8,%9}, {%0,%1,%2,%3};"
        : "+f"(c[0]), "+f"(c[1]), "+f"(c[2]), "+f"(c[3])
        : "r"(a[0]), "r"(a[1]), "r"(a[2]), "r"(a[3]), "r"(b[0]), "r"(b[1]));
}
__device__ __forceinline__ void cp16(uint32_t smem, const void* gmem) {
    asm volatile("cp.async.cg.shared.global [%0], [%1], 16;" :: "r"(smem), "l"(gmem));
}

// ---------------- pre-pass: split fp32 -> bf16 hi/lo ------------------------
__global__ __launch_bounds__(256, 4)
void split_kernel(const float* __restrict__ src, int n4)
{
    __nv_bfloat16* hi = g_xhi;
    __nv_bfloat16* lo = g_xlo;
    const int i = blockIdx.x * 256 + threadIdx.x;
    if (i >= n4) return;
    float4 v = ((const float4*)src)[i];
    __nv_bfloat16 h0 = __float2bfloat16(v.x);
    __nv_bfloat16 h1 = __float2bfloat16(v.y);
    __nv_bfloat16 h2 = __float2bfloat16(v.z);
    __nv_bfloat16 h3 = __float2bfloat16(v.w);
    hi[i*4+0] = h0; hi[i*4+1] = h1; hi[i*4+2] = h2; hi[i*4+3] = h3;
    lo[i*4+0] = __float2bfloat16(v.x - __bfloat162float(h0));
    lo[i*4+1] = __float2bfloat16(v.y - __bfloat162float(h1));
    lo[i*4+2] = __float2bfloat16(v.z - __bfloat162float(h2));
    lo[i*4+3] = __float2bfloat16(v.w - __bfloat162float(h3));
}

// ---------------- pre-pass: transpose-split weights [K,N] -> [N,K] ----------
template<int DST>
__global__ __launch_bounds__(256, 4)
void transpose_split_kernel(const float* __restrict__ w, int K, int N)
{
    __nv_bfloat16* hiT = DST ? g_wprojT_hi : g_wqkvT_hi;
    __nv_bfloat16* loT = DST ? g_wprojT_lo : g_wqkvT_lo;
    __shared__ float t[32][33];
    const int n0 = blockIdx.x * 32;
    const int k0 = blockIdx.y * 32;
    const int tx = threadIdx.x;           // 0..31
    const int ty = threadIdx.y;           // 0..7
    #pragma unroll
    for (int i = 0; i < 4; i++) {
        const int k = k0 + ty + i * 8;
        t[ty + i*8][tx] = w[(size_t)k * N + n0 + tx];
    }
    __syncthreads();
    #pragma unroll
    for (int i = 0; i < 4; i++) {
        const int n = n0 + ty + i * 8;
        const float v = t[tx][ty + i*8];
        __nv_bfloat16 h = __float2bfloat16(v);
        hiT[(size_t)n * K + k0 + tx] = h;
        loT[(size_t)n * K + k0 + tx] = __float2bfloat16(v - __bfloat162float(h));
    }
}

// ---------------- bf16 3-split tensor-core GEMM, cp.async double-buffered ----
// C[M,N] = A[M,K] * B[N,K]^T, 128x128x32 CTA tile, 8 warps (2x4), 64x32/warp.
// 3 terms: Ahi*Bhi + Alo*Bhi + Ahi*Blo, fp32 accumulate.

#define BK  32
#define LDA 40                       // padded smem stride (bf16 elems)
#define TILE_B (128*LDA*2)           // bytes per tile
#define GEMM_SMEM (2*4*TILE_B)       // 2 stages x {Ahi,Alo,Bhi,Blo} = 81920 B

template<int MODE>
__global__ __launch_bounds__(256, 2)
void gemm_mma_kernel(const float* __restrict__ bias, float* __restrict__ C)
{
    extern __shared__ __align__(16) char dsm[];
    const uint32_t u0 = smem_u32(dsm);

    const __nv_bfloat16* __restrict__ Ahi = MODE ? g_ahi : g_xhi;
    const __nv_bfloat16* __restrict__ Alo = MODE ? g_alo : g_xlo;
    const __nv_bfloat16* __restrict__ Bhi = MODE ? g_wprojT_hi : g_wqkvT_hi;
    const __nv_bfloat16* __restrict__ Blo = MODE ? g_wprojT_lo : g_wqkvT_lo;

    const int tid = threadIdx.x;
    const int wid = tid >> 5;
    const int lid = tid & 31;
    const int wm  = wid & 1;         // 0..1  (M)
    const int wn  = wid >> 1;        // 0..3  (N)
    const int m0  = blockIdx.y * 128;
    const int n0  = blockIdx.x * 128;

    // gmem load mapping: 64 rows/pass, 8 bf16 (16B) per thread, 2 passes
    const int lrow = tid >> 2;            // 0..63
    const int lcol = (tid & 3) * 8;       // 0,8,16,24

    const size_t gA0 = (size_t)(m0 + lrow)      * CDIM + lcol;
    const size_t gA1 = (size_t)(m0 + lrow + 64) * CDIM + lcol;
    const size_t gB0 = (size_t)(n0 + lrow)      * CDIM + lcol;
    const size_t gB1 = (size_t)(n0 + lrow + 64) * CDIM + lcol;
    const uint32_t so0 = (uint32_t)((lrow        * LDA + lcol) * 2);
    const uint32_t so1 = (uint32_t)(((lrow + 64) * LDA + lcol) * 2);

    // ldmatrix lane addressing
    const int aRow  = wm * 64 + (lid & 15);
    const int aKoff = (lid >> 4) * 8;
    const int bRow  = wn * 32 + (lid & 7);
    const int bKoff = ((lid >> 3) & 1) * 8;

    float acc[4][4][4];
    #pragma unroll
    for (int t = 0; t < 4; t++)
        #pragma unroll
        for (int u = 0; u < 4; u++)
            #pragma unroll
            for (int e = 0; e < 4; e++) acc[t][u][e] = 0.f;

#define ISSUE(chunk, stage) do {                                          \
        const int _k0 = (chunk) * BK;                                     \
        const uint32_t _sb = u0 + (stage) * 4 * TILE_B;                   \
        cp16(_sb + 0*TILE_B + so0, Ahi + gA0 + _k0);                      \
        cp16(_sb + 0*TILE_B + so1, Ahi + gA1 + _k0);                      \
        cp16(_sb + 1*TILE_B + so0, Alo + gA0 + _k0);                      \
        cp16(_sb + 1*TILE_B + so1, Alo + gA1 + _k0);                      \
        cp16(_sb + 2*TILE_B + so0, Bhi + gB0 + _k0);                      \
        cp16(_sb + 2*TILE_B + so1, Bhi + gB1 + _k0);                      \
        cp16(_sb + 3*TILE_B + so0, Blo + gB0 + _k0);                      \
        cp16(_sb + 3*TILE_B + so1, Blo + gB1 + _k0);                      \
        asm volatile("cp.async.commit_group;" ::: "memory");              \
    } while (0)

    ISSUE(0, 0);
    const int steps = CDIM / BK;     // 32

    for (int c = 0; c < steps; c++) {
        asm volatile("cp.async.wait_group 0;" ::: "memory");
        __syncthreads();
        if (c + 1 < steps) ISSUE(c + 1, (c + 1) & 1);

        const uint32_t sb  = u0 + (c & 1) * 4 * TILE_B;
        const uint32_t uAh = sb;
        const uint32_t uAl = sb + 1 * TILE_B;
        const uint32_t uBh = sb + 2 * TILE_B;
        const uint32_t uBl = sb + 3 * TILE_B;

        #pragma unroll
        for (int s = 0; s < 2; s++) {
            const int ak = aKoff + s * 16;
            const int bk = bKoff + s * 16;
            uint32_t ah[4][4], al[4][4], bh[4][2], bl[4][2];

            #pragma unroll
            for (int t = 0; t < 4; t++)
                ldsm4(ah[t], uAh + (uint32_t)(((aRow + t*16) * LDA + ak) * 2));
            #pragma unroll
            for (int u = 0; u < 4; u++)
                ldsm2(bh[u], uBh + (uint32_t)(((bRow + u*8) * LDA + bk) * 2));
            #pragma unroll
            for (int t = 0; t < 4; t++)
                #pragma unroll
                for (int u = 0; u < 4; u++)
                    mma16816(acc[t][u], ah[t], bh[u]);          // hi*hi

            #pragma unroll
            for (int t = 0; t < 4; t++)
                ldsm4(al[t], uAl + (uint32_t)(((aRow + t*16) * LDA + ak) * 2));
            #pragma unroll
            for (int t = 0; t < 4; t++)
                #pragma unroll
                for (int u = 0; u < 4; u++)
                    mma16816(acc[t][u], al[t], bh[u]);          // lo*hi

            #pragma unroll
            for (int u = 0; u < 4; u++)
                ldsm2(bl[u], uBl + (uint32_t)(((bRow + u*8) * LDA + bk) * 2));
            #pragma unroll
            for (int t = 0; t < 4; t++)
                #pragma unroll
                for (int u = 0; u < 4; u++)
                    mma16816(acc[t][u], ah[t], bl[u]);          // hi*lo
        }
    }
#undef ISSUE

    // ---- epilogue ----
    const int g   = lid >> 2;      // 0..7
    const int tig = lid & 3;       // 0..3
    #pragma unroll
    for (int t = 0; t < 4; t++) {
        #pragma unroll
        for (int u = 0; u < 4; u++) {
            #pragma unroll
            for (int e = 0; e < 4; e++) {
                const int m = m0 + wm*64 + t*16 + g + ((e >> 1) ? 8 : 0);
                const int n = n0 + wn*32 + u*8 + tig*2 + (e & 1);
                const float val = acc[t][u][e] + bias[n];
                if (MODE == 0) {
                    const int b_  = m >> 12;
                    const int l   = m & (LL - 1);
                    const int wch = n >> 10;
                    const int rem = n & 1023;
                    const int h   = rem >> 6;
                    const int dd  = rem & 63;
                    const size_t idx = (((size_t)(b_ * NH + h)) * LL + l) * HD + dd;
                    if (wch == 0)      g_q[idx] = val * QK_SCALE;
                    else if (wch == 1) g_k[idx] = val;
                    else               g_v[idx] = val;
                } else {
                    C[(size_t)m * CDIM + n] = val;
                }
            }
        }
    }
}

// ---------------- NA1D attention ---------------------------------------------
#define TROWS 140
#define ROWP  65

__global__ __launch_bounds__(128, 1)
void na1d_kernel(const float* __restrict__ rpb)
{
    __shared__ float tile[TROWS * ROWP];
    __shared__ float rsh[RPB_W];

    const int tid = threadIdx.x;
    const int l0  = blockIdx.x * 128;
    const int h   = blockIdx.y;
    const int b   = blockIdx.z;

    const size_t head_base = ((size_t)(b * NH + h)) * LL * HD;
    const int kbase = min(max(l0 - (KW / 2), 0), LL - KW);
    const int krows = min(TROWS, LL - kbase);

    const float* kp = g_k + head_base + (size_t)kbase * HD;
    for (int idx = tid; idx < krows * 16; idx += 128) {
        const int rr = idx >> 4;
        const int c4 = (idx & 15) * 4;
        float4 kv = *(const float4*)(kp + (size_t)rr * HD + c4);
        float* kd = &tile[rr * ROWP + c4];
        kd[0]=kv.x; kd[1]=kv.y; kd[2]=kv.z; kd[3]=kv.w;
    }
    if (tid < RPB_W) rsh[tid] = rpb[h * RPB_W + tid];
    __syncthreads();

    const int l = l0 + tid;
    float qreg[HD];
    const float* qp = g_q + head_base + (size_t)l * HD;
    #pragma unroll
    for (int c4 = 0; c4 < 16; c4++) {
        float4 qv = *(const float4*)(qp + c4 * 4);
        qreg[c4*4+0]=qv.x; qreg[c4*4+1]=qv.y; qreg[c4*4+2]=qv.z; qreg[c4*4+3]=qv.w;
    }

    const int ni = min(max(l - (KW / 2), 0), LL - KW);
    const int r0 = ni - kbase;
    const int bias0 = ni - l + (KW - 1);

    float logits[KW];
    #pragma unroll
    for (int kk = 0; kk < KW; kk++) {
        const float* kr = &tile[(r0 + kk) * ROWP];
        float s = 0.f;
        #pragma unroll
        for (int d = 0; d < HD; d++) s = fmaf(qreg[d], kr[d], s);
        logits[kk] = s + rsh[bias0 + kk];
    }

    float mx = logits[0];
    #pragma unroll
    for (int kk = 1; kk < KW; kk++) mx = fmaxf(mx, logits[kk]);
    float ssum = 0.f;
    #pragma unroll
    for (int kk = 0; kk < KW; kk++) { logits[kk] = expf(logits[kk] - mx); ssum += logits[kk]; }
    const float inv = 1.f / ssum;

    __syncthreads();
    const float* vp = g_v + head_base + (size_t)kbase * HD;
    for (int idx = tid; idx < krows * 16; idx += 128) {
        const int rr = idx >> 4;
        const int c4 = (idx & 15) * 4;
        float4 vv = *(const float4*)(vp + (size_t)rr * HD + c4);
        float* vd = &tile[rr * ROWP + c4];
        vd[0]=vv.x; vd[1]=vv.y; vd[2]=vv.z; vd[3]=vv.w;
    }
    __syncthreads();

    float accv[HD];
    #pragma unroll
    for (int d = 0; d < HD; d++) accv[d] = 0.f;
    #pragma unroll
    for (int kk = 0; kk < KW; kk++) {
        const float w = logits[kk] * inv;
        const float* vr = &tile[(r0 + kk) * ROWP];
        #pragma unroll
        for (int d = 0; d < HD; d++) accv[d] = fmaf(w, vr[d], accv[d]);
    }

    // write bf16 hi/lo into [B, L, H*D] for the proj GEMM
    const size_t obase = ((size_t)b * LL + l) * CDIM + h * HD;
    __nv_bfloat16* oh = g_ahi + obase;
    __nv_bfloat16* ol = g_alo + obase;
    #pragma unroll
    for (int d = 0; d < HD; d++) {
        const float v = accv[d];
        __nv_bfloat16 hh = __float2bfloat16(v);
        oh[d] = hh;
        ol[d] = __float2bfloat16(v - __bfloat162float(hh));
    }
}

// ---------------- launch ------------------------------------------------------
extern "C" void kernel_launch(void* const* d_in, const int* in_sizes, int n_in,
                              void* d_out, int out_size)
{
    const float* x      = (const float*)d_in[0];
    const float* w_qkv  = (const float*)d_in[1];
    const float* b_qkv  = (const float*)d_in[2];
    const float* rpb    = (const float*)d_in[3];
    const float* w_proj = (const float*)d_in[4];
    const float* b_proj = (const float*)d_in[5];
    float* out = (float*)d_out;

    cudaFuncSetAttribute(gemm_mma_kernel<0>, cudaFuncAttributeMaxDynamicSharedMemorySize, GEMM_SMEM);
    cudaFuncSetAttribute(gemm_mma_kernel<1>, cudaFuncAttributeMaxDynamicSharedMemorySize, GEMM_SMEM);

    // 0) split x into bf16 hi/lo
    {
        const int n4 = MM * CDIM / 4;
        split_kernel<<<(n4 + 255) / 256, 256>>>(x, n4);
    }
    // 0b) transpose+split weights
    {
        dim3 grid(NQKV / 32, CDIM / 32);
        transpose_split_kernel<0><<<grid, dim3(32, 8)>>>(w_qkv, CDIM, NQKV);
        dim3 grid2(CDIM / 32, CDIM / 32);
        transpose_split_kernel<1><<<grid2, dim3(32, 8)>>>(w_proj, CDIM, CDIM);
    }

    // 1) QKV GEMM (tensor cores) -> scatter q/k/v
    {
        dim3 grid(NQKV / 128, MM / 128);
        gemm_mma_kernel<0><<<grid, 256, GEMM_SMEM>>>(b_qkv, nullptr);
    }

    // 2) NA1D attention -> bf16 hi/lo attn output
    {
        dim3 grid(LL / 128, NH, BB);
        na1d_kernel<<<grid, 128>>>(rpb);
    }

    // 3) proj GEMM (tensor cores) -> d_out
    {
        dim3 grid(CDIM / 128, MM / 128);
        gemm_mma_kernel<1><<<grid, 256, GEMM_SMEM>>>(b_proj, out);
    }
}

// round 7
// speedup vs baseline: 2.7992x; 1.2832x over previous
#include <cuda_runtime.h>
#include <cuda_fp16.h>
#include <math.h>
#include <stdint.h>

#define NH   16
#define HD   64
#define KW   13
#define CDIM 1024
#define BB   4
#define LL   4096
#define MM   (BB*LL)        // 16384
#define NQKV (3*CDIM)       // 3072
#define QK_SCALE 0.125f
#define RPB_W (2*KW-1)      // 25

// ---------------- device-global scratch (no allocation allowed) --------------
__device__ float g_q[(size_t)BB*NH*LL*HD];
__device__ float g_k[(size_t)BB*NH*LL*HD];
__device__ float g_v[(size_t)BB*NH*LL*HD];

// activations split into fp16 hi/lo (both well within fp16 normal range)
__device__ __half g_xhi[(size_t)MM*CDIM];
__device__ __half g_xlo[(size_t)MM*CDIM];
__device__ __half g_ahi[(size_t)MM*CDIM];
__device__ __half g_alo[(size_t)MM*CDIM];

// weights: transposed [N,K], single fp16 (rounded)
__device__ __half g_wqkvT[(size_t)NQKV*CDIM];
__device__ __half g_wprojT[(size_t)CDIM*CDIM];

// ---------------- helpers (sm_80+ ISA, valid on sm_103 target) ---------------
__device__ __forceinline__ uint32_t smem_u32(const void* p) {
    uint32_t a;
    asm("{ .reg .u64 t; cvta.to.shared.u64 t, %1; cvt.u32.u64 %0, t; }"
        : "=r"(a) : "l"(p));
    return a;
}
__device__ __forceinline__ void ldsm4(uint32_t* r, uint32_t addr) {
    asm volatile("ldmatrix.sync.aligned.m8n8.x4.shared.b16 {%0,%1,%2,%3}, [%4];"
        : "=r"(r[0]), "=r"(r[1]), "=r"(r[2]), "=r"(r[3]) : "r"(addr));
}
__device__ __forceinline__ void ldsm2(uint32_t* r, uint32_t addr) {
    asm volatile("ldmatrix.sync.aligned.m8n8.x2.shared.b16 {%0,%1}, [%2];"
        : "=r"(r[0]), "=r"(r[1]) : "r"(addr));
}
__device__ __forceinline__ void mma16816(float* c, const uint32_t* a, const uint32_t* b) {
    asm volatile("mma.sync.aligned.m16n8k16.row.col.f32.f16.f16.f32 "
        "{%0,%1,%2,%3}, {%4,%5,%6,%7}, {%8,%9}, {%0,%1,%2,%3};"
        : "+f"(c[0]), "+f"(c[1]), "+f"(c[2]), "+f"(c[3])
        : "r"(a[0]), "r"(a[1]), "r"(a[2]), "r"(a[3]), "r"(b[0]), "r"(b[1]));
}
__device__ __forceinline__ void cp16(uint32_t smem, const void* gmem) {
    asm volatile("cp.async.cg.shared.global [%0], [%1], 16;" :: "r"(smem), "l"(gmem));
}

// ---------------- pre-pass: split fp32 x -> fp16 hi/lo ----------------------
__global__ __launch_bounds__(256, 4)
void split_kernel(const float* __restrict__ src, int n4)
{
    const int i = blockIdx.x * 256 + threadIdx.x;
    if (i >= n4) return;
    float4 v = ((const float4*)src)[i];
    __half h0 = __float2half(v.x);
    __half h1 = __float2half(v.y);
    __half h2 = __float2half(v.z);
    __half h3 = __float2half(v.w);
    g_xhi[i*4+0] = h0; g_xhi[i*4+1] = h1; g_xhi[i*4+2] = h2; g_xhi[i*4+3] = h3;
    g_xlo[i*4+0] = __float2half(v.x - __half2float(h0));
    g_xlo[i*4+1] = __float2half(v.y - __half2float(h1));
    g_xlo[i*4+2] = __float2half(v.z - __half2float(h2));
    g_xlo[i*4+3] = __float2half(v.w - __half2float(h3));
}

// ---------------- pre-pass: transpose weights [K,N] -> [N,K] fp16 -----------
template<int DST>
__global__ __launch_bounds__(256, 4)
void transpose_kernel(const float* __restrict__ w, int K, int N)
{
    __half* wT = DST ? g_wprojT : g_wqkvT;
    __shared__ float t[32][33];
    const int n0 = blockIdx.x * 32;
    const int k0 = blockIdx.y * 32;
    const int tx = threadIdx.x;           // 0..31
    const int ty = threadIdx.y;           // 0..7
    #pragma unroll
    for (int i = 0; i < 4; i++) {
        const int k = k0 + ty + i * 8;
        t[ty + i*8][tx] = w[(size_t)k * N + n0 + tx];
    }
    __syncthreads();
    #pragma unroll
    for (int i = 0; i < 4; i++) {
        const int n = n0 + ty + i * 8;
        wT[(size_t)n * K + k0 + tx] = __float2half(t[tx][ty + i*8]);
    }
}

// ---------------- fp16 2-term tensor-core GEMM, 3-stage cp.async ------------
// C[M,N] = (Ahi+Alo)[M,K] * B[N,K]^T, 128x128x32 CTA tile, 8 warps (2x4).
// 2 terms: Ahi*B + Alo*B, fp32 accumulate.

#define BK  32
#define LDA 40                       // padded smem stride (fp16 elems)
#define TILE_B (128*LDA*2)           // 10240 bytes per tile
#define STAGE_B (3*TILE_B)           // Ahi, Alo, B
#define NSTAGE 3
#define GEMM_SMEM (NSTAGE*STAGE_B)   // 92160 B

template<int MODE>
__global__ __launch_bounds__(256, 2)
void gemm_mma_kernel(const float* __restrict__ bias, float* __restrict__ C)
{
    extern __shared__ __align__(16) char dsm[];
    const uint32_t u0 = smem_u32(dsm);

    const __half* __restrict__ Ahi = MODE ? g_ahi : g_xhi;
    const __half* __restrict__ Alo = MODE ? g_alo : g_xlo;
    const __half* __restrict__ Bw  = MODE ? g_wprojT : g_wqkvT;

    const int tid = threadIdx.x;
    const int wid = tid >> 5;
    const int lid = tid & 31;
    const int wm  = wid & 1;         // 0..1  (M)
    const int wn  = wid >> 1;        // 0..3  (N)
    const int m0  = blockIdx.y * 128;
    const int n0  = blockIdx.x * 128;

    // gmem load mapping: 64 rows/pass, 8 fp16 (16B) per thread, 2 passes
    const int lrow = tid >> 2;            // 0..63
    const int lcol = (tid & 3) * 8;       // 0,8,16,24

    const size_t gA0 = (size_t)(m0 + lrow)      * CDIM + lcol;
    const size_t gA1 = (size_t)(m0 + lrow + 64) * CDIM + lcol;
    const size_t gB0 = (size_t)(n0 + lrow)      * CDIM + lcol;
    const size_t gB1 = (size_t)(n0 + lrow + 64) * CDIM + lcol;
    const uint32_t so0 = (uint32_t)((lrow        * LDA + lcol) * 2);
    const uint32_t so1 = (uint32_t)(((lrow + 64) * LDA + lcol) * 2);

    // ldmatrix lane addressing
    const int aRow  = wm * 64 + (lid & 15);
    const int aKoff = (lid >> 4) * 8;
    const int bRow  = wn * 32 + (lid & 7);
    const int bKoff = ((lid >> 3) & 1) * 8;

    float acc[4][4][4];
    #pragma unroll
    for (int t = 0; t < 4; t++)
        #pragma unroll
        for (int u = 0; u < 4; u++)
            #pragma unroll
            for (int e = 0; e < 4; e++) acc[t][u][e] = 0.f;

#define ISSUE(chunk, stage) do {                                          \
        const int _k0 = (chunk) * BK;                                     \
        const uint32_t _sb = u0 + (stage) * STAGE_B;                      \
        cp16(_sb + 0*TILE_B + so0, Ahi + gA0 + _k0);                      \
        cp16(_sb + 0*TILE_B + so1, Ahi + gA1 + _k0);                      \
        cp16(_sb + 1*TILE_B + so0, Alo + gA0 + _k0);                      \
        cp16(_sb + 1*TILE_B + so1, Alo + gA1 + _k0);                      \
        cp16(_sb + 2*TILE_B + so0, Bw  + gB0 + _k0);                      \
        cp16(_sb + 2*TILE_B + so1, Bw  + gB1 + _k0);                      \
        asm volatile("cp.async.commit_group;" ::: "memory");              \
    } while (0)

    const int steps = CDIM / BK;     // 32
    ISSUE(0, 0);
    ISSUE(1, 1);

    int stage = 0;
    for (int c = 0; c < steps; c++) {
        if (c + 1 < steps)
            asm volatile("cp.async.wait_group 1;" ::: "memory");
        else
            asm volatile("cp.async.wait_group 0;" ::: "memory");
        __syncthreads();

        // refill the stage freed at iteration c-1 (all warps past it)
        if (c + 2 < steps) {
            int ns = stage + 2; if (ns >= NSTAGE) ns -= NSTAGE;
            ISSUE(c + 2, ns);
        }

        const uint32_t sb  = u0 + stage * STAGE_B;
        const uint32_t uAh = sb;
        const uint32_t uAl = sb + 1 * TILE_B;
        const uint32_t uB  = sb + 2 * TILE_B;

        #pragma unroll
        for (int s = 0; s < 2; s++) {
            const int ak = aKoff + s * 16;
            const int bk = bKoff + s * 16;
            uint32_t ah[4][4], al[4][4], bw[4][2];

            #pragma unroll
            for (int t = 0; t < 4; t++)
                ldsm4(ah[t], uAh + (uint32_t)(((aRow + t*16) * LDA + ak) * 2));
            #pragma unroll
            for (int t = 0; t < 4; t++)
                ldsm4(al[t], uAl + (uint32_t)(((aRow + t*16) * LDA + ak) * 2));
            #pragma unroll
            for (int u = 0; u < 4; u++)
                ldsm2(bw[u], uB + (uint32_t)(((bRow + u*8) * LDA + bk) * 2));

            #pragma unroll
            for (int t = 0; t < 4; t++)
                #pragma unroll
                for (int u = 0; u < 4; u++)
                    mma16816(acc[t][u], ah[t], bw[u]);          // hi * W
            #pragma unroll
            for (int t = 0; t < 4; t++)
                #pragma unroll
                for (int u = 0; u < 4; u++)
                    mma16816(acc[t][u], al[t], bw[u]);          // lo * W
        }

        stage++; if (stage >= NSTAGE) stage = 0;
    }
#undef ISSUE

    // ---- epilogue ----
    const int g   = lid >> 2;      // 0..7
    const int tig = lid & 3;       // 0..3
    #pragma unroll
    for (int t = 0; t < 4; t++) {
        #pragma unroll
        for (int u = 0; u < 4; u++) {
            #pragma unroll
            for (int e = 0; e < 4; e++) {
                const int m = m0 + wm*64 + t*16 + g + ((e >> 1) ? 8 : 0);
                const int n = n0 + wn*32 + u*8 + tig*2 + (e & 1);
                const float val = acc[t][u][e] + bias[n];
                if (MODE == 0) {
                    const int b_  = m >> 12;
                    const int l   = m & (LL - 1);
                    const int wch = n >> 10;
                    const int rem = n & 1023;
                    const int h   = rem >> 6;
                    const int dd  = rem & 63;
                    const size_t idx = (((size_t)(b_ * NH + h)) * LL + l) * HD + dd;
                    if (wch == 0)      g_q[idx] = val * QK_SCALE;
                    else if (wch == 1) g_k[idx] = val;
                    else               g_v[idx] = val;
                } else {
                    C[(size_t)m * CDIM + n] = val;
                }
            }
        }
    }
}

// ---------------- NA1D attention ---------------------------------------------
#define TROWS 140
#define ROWP  65

__global__ __launch_bounds__(128, 1)
void na1d_kernel(const float* __restrict__ rpb)
{
    __shared__ float tile[TROWS * ROWP];
    __shared__ float rsh[RPB_W];

    const int tid = threadIdx.x;
    const int l0  = blockIdx.x * 128;
    const int h   = blockIdx.y;
    const int b   = blockIdx.z;

    const size_t head_base = ((size_t)(b * NH + h)) * LL * HD;
    const int kbase = min(max(l0 - (KW / 2), 0), LL - KW);
    const int krows = min(TROWS, LL - kbase);

    const float* kp = g_k + head_base + (size_t)kbase * HD;
    for (int idx = tid; idx < krows * 16; idx += 128) {
        const int rr = idx >> 4;
        const int c4 = (idx & 15) * 4;
        float4 kv = *(const float4*)(kp + (size_t)rr * HD + c4);
        float* kd = &tile[rr * ROWP + c4];
        kd[0]=kv.x; kd[1]=kv.y; kd[2]=kv.z; kd[3]=kv.w;
    }
    if (tid < RPB_W) rsh[tid] = rpb[h * RPB_W + tid];
    __syncthreads();

    const int l = l0 + tid;
    float qreg[HD];
    const float* qp = g_q + head_base + (size_t)l * HD;
    #pragma unroll
    for (int c4 = 0; c4 < 16; c4++) {
        float4 qv = *(const float4*)(qp + c4 * 4);
        qreg[c4*4+0]=qv.x; qreg[c4*4+1]=qv.y; qreg[c4*4+2]=qv.z; qreg[c4*4+3]=qv.w;
    }

    const int ni = min(max(l - (KW / 2), 0), LL - KW);
    const int r0 = ni - kbase;
    const int bias0 = ni - l + (KW - 1);

    float logits[KW];
    #pragma unroll
    for (int kk = 0; kk < KW; kk++) {
        const float* kr = &tile[(r0 + kk) * ROWP];
        float s = 0.f;
        #pragma unroll
        for (int d = 0; d < HD; d++) s = fmaf(qreg[d], kr[d], s);
        logits[kk] = s + rsh[bias0 + kk];
    }

    float mx = logits[0];
    #pragma unroll
    for (int kk = 1; kk < KW; kk++) mx = fmaxf(mx, logits[kk]);
    float ssum = 0.f;
    #pragma unroll
    for (int kk = 0; kk < KW; kk++) { logits[kk] = expf(logits[kk] - mx); ssum += logits[kk]; }
    const float inv = 1.f / ssum;

    __syncthreads();
    const float* vp = g_v + head_base + (size_t)kbase * HD;
    for (int idx = tid; idx < krows * 16; idx += 128) {
        const int rr = idx >> 4;
        const int c4 = (idx & 15) * 4;
        float4 vv = *(const float4*)(vp + (size_t)rr * HD + c4);
        float* vd = &tile[rr * ROWP + c4];
        vd[0]=vv.x; vd[1]=vv.y; vd[2]=vv.z; vd[3]=vv.w;
    }
    __syncthreads();

    float accv[HD];
    #pragma unroll
    for (int d = 0; d < HD; d++) accv[d] = 0.f;
    #pragma unroll
    for (int kk = 0; kk < KW; kk++) {
        const float w = logits[kk] * inv;
        const float* vr = &tile[(r0 + kk) * ROWP];
        #pragma unroll
        for (int d = 0; d < HD; d++) accv[d] = fmaf(w, vr[d], accv[d]);
    }

    // write fp16 hi/lo into [B, L, H*D] for the proj GEMM
    const size_t obase = ((size_t)b * LL + l) * CDIM + h * HD;
    __half* oh = g_ahi + obase;
    __half* ol = g_alo + obase;
    #pragma unroll
    for (int d = 0; d < HD; d++) {
        const float v = accv[d];
        __half hh = __float2half(v);
        oh[d] = hh;
        ol[d] = __float2half(v - __half2float(hh));
    }
}

// ---------------- launch ------------------------------------------------------
extern "C" void kernel_launch(void* const* d_in, const int* in_sizes, int n_in,
                              void* d_out, int out_size)
{
    const float* x      = (const float*)d_in[0];
    const float* w_qkv  = (const float*)d_in[1];
    const float* b_qkv  = (const float*)d_in[2];
    const float* rpb    = (const float*)d_in[3];
    const float* w_proj = (const float*)d_in[4];
    const float* b_proj = (const float*)d_in[5];
    float* out = (float*)d_out;

    cudaFuncSetAttribute(gemm_mma_kernel<0>, cudaFuncAttributeMaxDynamicSharedMemorySize, GEMM_SMEM);
    cudaFuncSetAttribute(gemm_mma_kernel<1>, cudaFuncAttributeMaxDynamicSharedMemorySize, GEMM_SMEM);

    // 0) split x into fp16 hi/lo
    {
        const int n4 = MM * CDIM / 4;
        split_kernel<<<(n4 + 255) / 256, 256>>>(x, n4);
    }
    // 0b) transpose weights -> fp16 [N,K]
    {
        dim3 grid(NQKV / 32, CDIM / 32);
        transpose_kernel<0><<<grid, dim3(32, 8)>>>(w_qkv, CDIM, NQKV);
        dim3 grid2(CDIM / 32, CDIM / 32);
        transpose_kernel<1><<<grid2, dim3(32, 8)>>>(w_proj, CDIM, CDIM);
    }

    // 1) QKV GEMM (tensor cores) -> scatter q/k/v
    {
        dim3 grid(NQKV / 128, MM / 128);
        gemm_mma_kernel<0><<<grid, 256, GEMM_SMEM>>>(b_qkv, nullptr);
    }

    // 2) NA1D attention -> fp16 hi/lo attn output
    {
        dim3 grid(LL / 128, NH, BB);
        na1d_kernel<<<grid, 128>>>(rpb);
    }

    // 3) proj GEMM (tensor cores) -> d_out
    {
        dim3 grid(CDIM / 128, MM / 128);
        gemm_mma_kernel<1><<<grid, 256, GEMM_SMEM>>>(b_proj, out);
    }
}